// round 4
// baseline (speedup 1.0000x reference)
#include <cuda_runtime.h>
#include <math.h>

// Problem constants (fixed by the dataset)
#define N_NODES 3072
#define IN_DIM  512
#define HD      512      // H*D
#define D       64
#define E_EDGES 98304
#define COL0    448      // start column of head 7 in the H*D projection

// ---------------- scratch (device globals: allocation-free) ----------------
__device__ float g_xsum[IN_DIM];                 // column sums of x
__device__ float g_mv[HD];                       // xsum . Wv[:,j]  (raw dot, no bias)
__device__ float g_q7[N_NODES * D];
__device__ float g_k7[N_NODES * D];
__device__ float g_v7[N_NODES * D];
__device__ float g_acc[N_NODES * D];             // sum_{edges} (e^s-1) * v7[dst]
__device__ float g_Z[N_NODES];                   // sum_{edges} (e^s-1)
__device__ int   g_is64;                         // edge_index dtype flag
__device__ unsigned int g_bitmap[(N_NODES * N_NODES) / 32];  // edge dedupe, 1.125 MB

// ---------------- zero scratch + dtype sniff (graph-replay safe) -----------
__global__ void zero_kernel(const int* __restrict__ ei32) {
    int i = blockIdx.x * blockDim.x + threadIdx.x;
    int stride = gridDim.x * blockDim.x;
    for (int j = i; j < N_NODES * D; j += stride) g_acc[j] = 0.f;
    for (int j = i; j < (N_NODES * N_NODES) / 32; j += stride) g_bitmap[j] = 0u;
    for (int j = i; j < N_NODES; j += stride) g_Z[j] = 0.f;
    if (i < IN_DIM) { g_xsum[i] = 0.f; g_mv[i] = 0.f; }
    if (blockIdx.x == 0 && threadIdx.x == 0) {
        // int64 layout => words 1,3,5,... are high halves of values < 3072 => all 0.
        // int32 layout => they are random node ids; any nonzero proves int32.
        int any = 0;
        for (int w = 1; w < 256; w += 2) any |= ei32[w];
        g_is64 = (any == 0) ? 1 : 0;
    }
}

// ---------------- column sums of x: 24 blocks x 512 threads ----------------
__global__ void colsum_kernel(const float* __restrict__ x) {
    int c  = threadIdx.x;          // 0..511 -> column
    int r0 = blockIdx.x * 128;     // 24 blocks * 128 rows
    float s = 0.f;
#pragma unroll 8
    for (int r = 0; r < 128; r++) s += x[(r0 + r) * IN_DIM + c];
    atomicAdd(&g_xsum[c], s);
}

// ---------------- q7/k7/v7 = x @ W[:,448:512] + b  (fp32 tiled GEMM) -------
// grid (48, 3): 48 row tiles of 64, y selects Wq/Wk/Wv. 256 threads,
// BM=64 BN=64 BK=16, 4x4 register tile per thread.
__global__ void proj_kernel(const float* __restrict__ x,
                            const float* __restrict__ Wq,
                            const float* __restrict__ Wk,
                            const float* __restrict__ Wv,
                            const float* __restrict__ bq,
                            const float* __restrict__ bk,
                            const float* __restrict__ bv) {
    const float* W; const float* b; float* out;
    if      (blockIdx.y == 0) { W = Wq; b = bq; out = g_q7; }
    else if (blockIdx.y == 1) { W = Wk; b = bk; out = g_k7; }
    else                      { W = Wv; b = bv; out = g_v7; }

    __shared__ __align__(16) float xsT[16][68];  // [k][row], padded
    __shared__ __align__(16) float ws[16][64];   // [k][col]

    int tid = threadIdx.x;
    int tx = tid & 15;          // col group
    int ty = tid >> 4;          // row group
    int row0 = blockIdx.x * 64;

    float acc[4][4] = {};

    for (int k0 = 0; k0 < IN_DIM; k0 += 16) {
        {
            int r  = tid >> 2;           // 0..63
            int kk = (tid & 3) * 4;      // 0,4,8,12
            float4 v = *(const float4*)&x[(row0 + r) * IN_DIM + k0 + kk];
            xsT[kk + 0][r] = v.x; xsT[kk + 1][r] = v.y;
            xsT[kk + 2][r] = v.z; xsT[kk + 3][r] = v.w;
        }
        {
            int kk = tid >> 4;           // 0..15
            int c4 = (tid & 15) * 4;
            *(float4*)&ws[kk][c4] =
                *(const float4*)&W[(k0 + kk) * HD + COL0 + c4];
        }
        __syncthreads();
#pragma unroll
        for (int k = 0; k < 16; k++) {
            float4 a  = *(const float4*)&xsT[k][ty * 4];
            float4 bb = *(const float4*)&ws[k][tx * 4];
            float av[4]  = {a.x, a.y, a.z, a.w};
            float bv4[4] = {bb.x, bb.y, bb.z, bb.w};
#pragma unroll
            for (int i = 0; i < 4; i++)
#pragma unroll
                for (int j = 0; j < 4; j++)
                    acc[i][j] += av[i] * bv4[j];
        }
        __syncthreads();
    }

#pragma unroll
    for (int i = 0; i < 4; i++) {
        int r = row0 + ty * 4 + i;
#pragma unroll
        for (int j = 0; j < 4; j++) {
            int c = tx * 4 + j;
            out[r * D + c] = acc[i][j] + b[COL0 + c];
        }
    }
}

// ---------------- g_mv[j] = xsum . Wv[:,j] (split-K over 16 blocks) --------
__global__ void mv_kernel(const float* __restrict__ Wv) {
    int j  = threadIdx.x;       // 0..511
    int k0 = blockIdx.x * 32;   // 16 blocks
    float s = 0.f;
#pragma unroll 8
    for (int k = 0; k < 32; k++) s += g_xsum[k0 + k] * Wv[(k0 + k) * HD + j];
    atomicAdd(&g_mv[j], s);
}

// ---------------- edges: score, dedupe, scatter-accumulate -----------------
// one warp per edge; dtype-agnostic edge fetch via g_is64
__global__ void edge_kernel(const int* __restrict__ ei32) {
    int warp = (blockIdx.x * blockDim.x + threadIdx.x) >> 5;
    int lane = threadIdx.x & 31;
    if (warp >= E_EDGES) return;

    int src = 0, dst = 0;
    if (lane == 0) {
        if (g_is64) {   // little-endian int64: low word at 2*idx
            src = ei32[2 * warp];
            dst = ei32[2 * (E_EDGES + warp)];
        } else {        // int32
            src = ei32[warp];
            dst = ei32[E_EDGES + warp];
        }
    }
    src = __shfl_sync(0xffffffffu, src, 0);
    dst = __shfl_sync(0xffffffffu, dst, 0);

    const float2* q = (const float2*)(g_q7 + src * D);
    const float2* k = (const float2*)(g_k7 + dst * D);
    float2 qv = q[lane];
    float2 kv = k[lane];
    float p = qv.x * kv.x + qv.y * kv.y;
#pragma unroll
    for (int o = 16; o; o >>= 1) p += __shfl_xor_sync(0xffffffffu, p, o);
    float s = p * 0.125f;   // / sqrt(64)

    // dedupe: the dense masked matrix holds each (src,dst) cell exactly once
    unsigned keep = 0;
    if (lane == 0) {
        unsigned bit  = (unsigned)src * N_NODES + (unsigned)dst;
        unsigned word = bit >> 5;
        unsigned m    = 1u << (bit & 31);
        unsigned old  = atomicOr(&g_bitmap[word], m);
        keep = (old & m) ? 0u : 1u;
    }
    keep = __shfl_sync(0xffffffffu, keep, 0);
    if (!keep) return;

    float w = expm1f(s);                     // e^s - 1
    const float2* v = (const float2*)(g_v7 + dst * D);
    float2 vv = v[lane];
    atomicAdd(&g_acc[src * D + 2 * lane],     w * vv.x);
    atomicAdd(&g_acc[src * D + 2 * lane + 1], w * vv.y);
    if (lane == 0) atomicAdd(&g_Z[src], w);
}

// ---------------- finalize output ------------------------------------------
__global__ void final_kernel(const float* __restrict__ bv,
                             float* __restrict__ out) {
    int idx = blockIdx.x * blockDim.x + threadIdx.x;
    if (idx >= N_NODES * HD) return;
    int n = idx >> 9;        // / 512
    int c = idx & 511;
    float r;
    if (c < COL0) {
        // heads 0..6: uniform softmax -> broadcast mean of v
        r = g_mv[c] * (1.f / N_NODES) + bv[c];
    } else {
        int d = c - COL0;
        float vsum = g_mv[c] + (float)N_NODES * bv[c];   // sum_m v7[m,d]
        float num  = vsum + g_acc[n * D + d];
        float den  = (float)N_NODES + g_Z[n];
        r = num / den;
    }
    out[idx] = r;
}

// ---------------------------------------------------------------------------
extern "C" void kernel_launch(void* const* d_in, const int* in_sizes, int n_in,
                              void* d_out, int out_size) {
    const float* x    = (const float*)d_in[0];
    const int*   ei32 = (const int*)d_in[1];     // int32 OR int64 (sniffed on device)
    const float* Wq   = (const float*)d_in[2];
    const float* Wk   = (const float*)d_in[3];
    const float* Wv   = (const float*)d_in[4];
    const float* bq   = (const float*)d_in[5];
    const float* bk   = (const float*)d_in[6];
    const float* bv   = (const float*)d_in[7];
    float* out = (float*)d_out;

    zero_kernel<<<1024, 256>>>(ei32);
    colsum_kernel<<<24, 512>>>(x);
    proj_kernel<<<dim3(48, 3), 256>>>(x, Wq, Wk, Wv, bq, bk, bv);
    mv_kernel<<<16, 512>>>(Wv);
    edge_kernel<<<E_EDGES / 8, 256>>>(ei32);
    final_kernel<<<(N_NODES * HD + 255) / 256, 256>>>(bv, out);
}